// round 8
// baseline (speedup 1.0000x reference)
#include <cuda_runtime.h>
#include <cuda_bf16.h>
#include <cstdint>
#include <cstddef>

#define N_NODES 50000
#define IN_DIM  512
#define HDIM    2048
#define OUT_DIM 512

// ---------------------------------------------------------------------------
// Device-global scratch (allocation-free per harness rules).
// Split-bf16 operands stored compact as [hi | lo] (width 2K); the GEMM tile
// loaders expand to the 3-term product via k-tile remapping.
// ---------------------------------------------------------------------------
__device__ float4 g_aggv[(size_t)N_NODES * 128];                    // agg fp32 (512/row)
__device__ float4 g_A1v [(size_t)N_NODES * 2048 / 8];               // [hi|lo] of h   (K=1024)
__device__ float4 g_A2v [(size_t)N_NODES * 4096 / 8];               // [hi|lo] layer1 (K=2048)
__device__ float4 g_A3v [(size_t)N_NODES * 4096 / 8];               // [hi|lo] layer2 (K=2048)
__device__ float4 g_W1tv[(size_t)HDIM    * 2048 / 8];               // [N, 2K] transposed
__device__ float4 g_W2tv[(size_t)HDIM    * 4096 / 8];
__device__ float4 g_W3tv[(size_t)OUT_DIM * 4096 / 8];

// ---------------------------------------------------------------------------
// PTX helpers (base compute_103 features only: cp.async / ldmatrix / mma.sync)
// ---------------------------------------------------------------------------
__device__ __forceinline__ uint32_t smem_u32(const void* p) {
    uint32_t a;
    asm("{ .reg .u64 t; cvta.to.shared.u64 t, %1; cvt.u32.u64 %0, t; }"
        : "=r"(a) : "l"(p));
    return a;
}
__device__ __forceinline__ void cp_async16(uint32_t dst, const void* src, bool pred) {
    int sz = pred ? 16 : 0;
    asm volatile("cp.async.cg.shared.global [%0], [%1], 16, %2;"
                 :: "r"(dst), "l"(src), "r"(sz));
}
__device__ __forceinline__ void cp_commit() { asm volatile("cp.async.commit_group;"); }
__device__ __forceinline__ void cp_wait1()  { asm volatile("cp.async.wait_group 1;" ::: "memory"); }
__device__ __forceinline__ void cp_wait0()  { asm volatile("cp.async.wait_group 0;" ::: "memory"); }

__device__ __forceinline__ void ldmx4(uint32_t& r0, uint32_t& r1, uint32_t& r2, uint32_t& r3,
                                      uint32_t addr) {
    asm volatile("ldmatrix.sync.aligned.m8n8.x4.shared.b16 {%0,%1,%2,%3}, [%4];"
                 : "=r"(r0), "=r"(r1), "=r"(r2), "=r"(r3) : "r"(addr));
}
__device__ __forceinline__ void mma16816(float* c, const uint32_t* a, const uint32_t* b) {
    asm volatile(
        "mma.sync.aligned.m16n8k16.row.col.f32.bf16.bf16.f32 "
        "{%0,%1,%2,%3}, {%4,%5,%6,%7}, {%8,%9}, {%0,%1,%2,%3};"
        : "+f"(c[0]), "+f"(c[1]), "+f"(c[2]), "+f"(c[3])
        : "r"(a[0]), "r"(a[1]), "r"(a[2]), "r"(a[3]), "r"(b[0]), "r"(b[1]));
}
__device__ __forceinline__ void red_add_v4(float* p, float4 v) {
    asm volatile("red.global.add.v4.f32 [%0], {%1,%2,%3,%4};"
                 :: "l"(p), "f"(v.x), "f"(v.y), "f"(v.z), "f"(v.w) : "memory");
}
__device__ __forceinline__ uint32_t swz(uint32_t off) {       // SW128 swizzle
    return off ^ ((off >> 3) & 0x70);
}
// k-tile remap for in-loader 3-term split expansion:
// logical regions over A: {hi, hi, lo};  over B: {hi, lo, hi}
__device__ __forceinline__ int skt_a(int kt, int T1) { return (kt < T1) ? kt : kt - T1; }
__device__ __forceinline__ int skt_b(int kt, int T1) { return (kt < 2 * T1) ? kt : kt - 2 * T1; }

// ---------------------------------------------------------------------------
// Kernel 1: zero the aggregation buffer
// ---------------------------------------------------------------------------
__global__ void zero_agg_kernel(int n)
{
    long long i = (long long)blockIdx.x * blockDim.x + threadIdx.x;
    long long total = (long long)n * 128;
    if (i >= total) return;
    g_aggv[i] = make_float4(0.f, 0.f, 0.f, 0.f);
}

// ---------------------------------------------------------------------------
// Kernel 2: fused weight converts. W [K,N] fp32 -> Wt [N, 2K] bf16 [hi|lo]
// via 32x32 smem tile transpose. blockIdx.z selects the weight.
// ---------------------------------------------------------------------------
__global__ void convert_w_all(const float* __restrict__ W1, const float* __restrict__ W2,
                              const float* __restrict__ W3)
{
    __shared__ float tile[32][33];
    const float* W; __nv_bfloat16* Wt; int K, N;
    if (blockIdx.z == 0)      { W = W1; Wt = (__nv_bfloat16*)g_W1tv; K = 1024; N = 2048; }
    else if (blockIdx.z == 1) { W = W2; Wt = (__nv_bfloat16*)g_W2tv; K = 2048; N = 2048; }
    else                      { W = W3; Wt = (__nv_bfloat16*)g_W3tv; K = 2048; N = 512;  }
    const int k0 = blockIdx.y * 32;
    const int n0 = blockIdx.x * 32;
    if (k0 >= K || n0 >= N) return;
    const int tx = threadIdx.x;
#pragma unroll
    for (int r = threadIdx.y; r < 32; r += 8)
        tile[r][tx] = W[(size_t)(k0 + r) * N + n0 + tx];
    __syncthreads();
#pragma unroll
    for (int r = threadIdx.y; r < 32; r += 8) {
        int n = n0 + r;
        int k = k0 + tx;
        float v = tile[tx][r];
        __nv_bfloat16 hi = __float2bfloat16(v);
        __nv_bfloat16 lo = __float2bfloat16(v - __bfloat162float(hi));
        size_t base = (size_t)n * (2 * (size_t)K);
        Wt[base + k]     = hi;
        Wt[base + K + k] = lo;
    }
}

// ---------------------------------------------------------------------------
// Kernel 3: SpMM scatter (warp per edge) — vectorized fp32 atomics (red.v4)
// ---------------------------------------------------------------------------
__global__ void spmm_kernel(const float* __restrict__ x, const float* __restrict__ ew,
                            const int* __restrict__ src, const int* __restrict__ dst, int E)
{
    int w    = (blockIdx.x * blockDim.x + threadIdx.x) >> 5;
    int lane = threadIdx.x & 31;
    if (w >= E) return;
    int   s  = __ldg(src + w);
    int   d  = __ldg(dst + w);
    float wt = __ldg(ew + w);
    const float4* xs = (const float4*)(x + (long long)s * IN_DIM);
    float4* out4 = g_aggv + (long long)d * 128;
#pragma unroll
    for (int i = 0; i < 4; i++) {
        int idx = lane + 32 * i;
        float4 v = __ldg(xs + idx);
        float4 m = make_float4(wt * v.x, wt * v.y, wt * v.z, wt * v.w);
        red_add_v4((float*)(out4 + idx), m);
    }
}

// ---------------------------------------------------------------------------
// Kernel 4: split-convert [x | agg] -> A1 [hi|lo] bf16 [M, 2048]
// ---------------------------------------------------------------------------
__global__ void convert_h_kernel(const float* __restrict__ x, int M)
{
    __nv_bfloat16* A1 = (__nv_bfloat16*)g_A1v;
    size_t i = (size_t)blockIdx.x * blockDim.x + threadIdx.x;   // float2 units
    size_t total = (size_t)M * 512;
    if (i >= total) return;
    int m  = (int)(i >> 9);
    int k2 = (int)(i & 511);
    float2 v = (k2 < 256)
        ? ((const float2*)x)[(size_t)m * 256 + k2]
        : ((const float2*)g_aggv)[(size_t)m * 256 + (k2 - 256)];
    __nv_bfloat16 h0 = __float2bfloat16(v.x), h1 = __float2bfloat16(v.y);
    __nv_bfloat16 l0 = __float2bfloat16(v.x - __bfloat162float(h0));
    __nv_bfloat16 l1 = __float2bfloat16(v.y - __bfloat162float(h1));
    __nv_bfloat162* row = (__nv_bfloat162*)(A1 + (size_t)m * 2048);
    row[k2]       = __halves2bfloat162(h0, h1);
    row[512 + k2] = __halves2bfloat162(l0, l1);
}

// ---------------------------------------------------------------------------
// Kernel 5: HMMA (mma.sync bf16) GEMM with in-loader 3-term split expansion.
//   C[M,Nc] = act(A[M,2K]{hi|lo} *split* Bt[Nc,2K]{hi|lo}^T + bias)
// Logical K' = 3K: region0 = Ahi*Bhi, region1 = Ahi*Blo, region2 = Alo*Bhi.
// BM=128, BN=256, BK=64, 8 warps (warp tile 32x128), 3-stage cp.async ring,
// single __syncthreads per k-tile, SW128 smem, ldmatrix fragment loads.
// PACK: write [hi|lo] split output with row stride 2*Nc.
// ---------------------------------------------------------------------------
#define STAGE_BYTES 49152           // 16KB A + 32KB B
#define SMEM_BYTES  (3 * STAGE_BYTES)

__device__ __forceinline__ void load_tile_A(const __nv_bfloat16* A, int bm, int M, int strideA,
                                            int skt, uint32_t sdst, int tid)
{
#pragma unroll
    for (int i = 0; i < 4; i++) {
        int c = tid + i * 256;              // 0..1023 16B-chunks (128 rows x 8)
        int row = c >> 3, c16 = c & 7;
        int rm = bm + row;
        bool ok = rm < M;
        int rs = ok ? rm : (M - 1);
        const void* src = (const char*)(A + (size_t)rs * strideA + skt * 64) + c16 * 16;
        cp_async16(sdst + swz(row * 128 + c16 * 16), src, ok);
    }
}
__device__ __forceinline__ void load_tile_B(const __nv_bfloat16* Bt, int bn, int strideB,
                                            int skt, uint32_t sdst, int tid)
{
#pragma unroll
    for (int i = 0; i < 8; i++) {
        int c = tid + i * 256;              // 0..2047 (256 rows x 8)
        int row = c >> 3, c16 = c & 7;
        const void* src = (const char*)(Bt + (size_t)(bn + row) * strideB + skt * 64) + c16 * 16;
        cp_async16(sdst + swz(row * 128 + c16 * 16), src, true);
    }
}

template <bool RELU, bool PACK>
__global__ void __launch_bounds__(256, 1)
hmma_gemm(const __nv_bfloat16* __restrict__ A, const __nv_bfloat16* __restrict__ Bt,
          const float* __restrict__ bias, void* __restrict__ Cout,
          int M, int K, int Nc)
{
    extern __shared__ __align__(1024) char smem[];
    const uint32_t sb = smem_u32(smem);
    const int tid  = threadIdx.x;
    const int wid  = tid >> 5;
    const int lane = tid & 31;
    const int warp_m = wid & 3;        // 4 warps along M (32 rows each)
    const int warp_n = wid >> 2;       // 2 warps along N (128 cols each)
    const int bm = blockIdx.y * 128;
    const int bn = blockIdx.x * 256;
    const int strideA = 2 * K;         // stored width
    const int strideB = 2 * K;

    const int j = lane >> 3;
    const int r = lane & 7;

    float acc[2][16][4];
#pragma unroll
    for (int mt = 0; mt < 2; mt++)
#pragma unroll
        for (int nt = 0; nt < 16; nt++)
#pragma unroll
            for (int q = 0; q < 4; q++) acc[mt][nt][q] = 0.f;

    const int T1 = K / 64;             // tiles per K region
    const int T  = 3 * T1;             // logical k-tiles

    // prologue: stages 0,1
    load_tile_A(A, bm, M, strideA, skt_a(0, T1), sb + 0 * STAGE_BYTES, tid);
    load_tile_B(Bt, bn, strideB, skt_b(0, T1), sb + 0 * STAGE_BYTES + 16384, tid);
    cp_commit();
    load_tile_A(A, bm, M, strideA, skt_a(1, T1), sb + 1 * STAGE_BYTES, tid);
    load_tile_B(Bt, bn, strideB, skt_b(1, T1), sb + 1 * STAGE_BYTES + 16384, tid);
    cp_commit();

    const int amrow0 = warp_m * 32 + (j & 1) * 8 + r;    // + mt*16
    const int akoff  = (j >> 1) * 16;                    // + ks*32 bytes
    const int bnrow0 = warp_n * 128 + (j >> 1) * 8 + r;  // + nb*16
    const int bkoff  = (j & 1) * 16;

    int stage = 0;
    for (int kt = 0; kt < T; kt++) {
        if (kt == T - 1) cp_wait0(); else cp_wait1();
        __syncthreads();
        const uint32_t sA = sb + stage * STAGE_BYTES;
        const uint32_t sB = sA + 16384;

#pragma unroll
        for (int ks = 0; ks < 4; ks++) {
            uint32_t a[2][4], b[16][2];
#pragma unroll
            for (int mt = 0; mt < 2; mt++) {
                uint32_t addr = sA + swz((uint32_t)(amrow0 + mt * 16) * 128 +
                                         (uint32_t)(ks * 32 + akoff));
                ldmx4(a[mt][0], a[mt][1], a[mt][2], a[mt][3], addr);
            }
#pragma unroll
            for (int nb = 0; nb < 8; nb++) {
                uint32_t addr = sB + swz((uint32_t)(bnrow0 + nb * 16) * 128 +
                                         (uint32_t)(ks * 32 + bkoff));
                uint32_t t0, t1, t2, t3;
                ldmx4(t0, t1, t2, t3, addr);
                b[2 * nb][0] = t0; b[2 * nb][1] = t1;
                b[2 * nb + 1][0] = t2; b[2 * nb + 1][1] = t3;
            }
#pragma unroll
            for (int mt = 0; mt < 2; mt++)
#pragma unroll
                for (int nt = 0; nt < 16; nt++)
                    mma16816(acc[mt][nt], a[mt], b[nt]);
        }

        if (kt + 2 < T) {
            int ns = stage + 2; if (ns >= 3) ns -= 3;
            load_tile_A(A, bm, M, strideA, skt_a(kt + 2, T1), sb + ns * STAGE_BYTES, tid);
            load_tile_B(Bt, bn, strideB, skt_b(kt + 2, T1), sb + ns * STAGE_BYTES + 16384, tid);
            cp_commit();
        }
        if (++stage == 3) stage = 0;
    }

    // ------------------------- epilogue -------------------------
    const int row0 = bm + warp_m * 32;
    const int col0 = bn + warp_n * 128;
#pragma unroll
    for (int mt = 0; mt < 2; mt++) {
#pragma unroll
        for (int nt = 0; nt < 16; nt++) {
            const int gc = col0 + nt * 8 + 2 * (lane & 3);
            const float bi0 = __ldg(bias + gc);
            const float bi1 = __ldg(bias + gc + 1);
#pragma unroll
            for (int half = 0; half < 2; half++) {
                const int m = row0 + mt * 16 + (lane >> 2) + half * 8;
                if (m >= M) continue;
                float v0 = acc[mt][nt][half * 2 + 0] + bi0;
                float v1 = acc[mt][nt][half * 2 + 1] + bi1;
                if (RELU) { v0 = fmaxf(v0, 0.f); v1 = fmaxf(v1, 0.f); }
                if (PACK) {
                    __nv_bfloat16 h0 = __float2bfloat16(v0), h1 = __float2bfloat16(v1);
                    __nv_bfloat16 l0 = __float2bfloat16(v0 - __bfloat162float(h0));
                    __nv_bfloat16 l1 = __float2bfloat16(v1 - __bfloat162float(h1));
                    __nv_bfloat16* O = (__nv_bfloat16*)Cout;
                    const size_t base = (size_t)m * (2 * (size_t)Nc);
                    *(__nv_bfloat162*)(O + base + gc)      = __halves2bfloat162(h0, h1);
                    *(__nv_bfloat162*)(O + base + Nc + gc) = __halves2bfloat162(l0, l1);
                } else {
                    float* O = (float*)Cout;
                    *(float2*)(O + (size_t)m * Nc + gc) = make_float2(v0, v1);
                }
            }
        }
    }
}

// ---------------------------------------------------------------------------
// Launcher. Order puts GEMM2 at kernel-launch #6 (ncu -s 5 -c 1 profiles it).
// ---------------------------------------------------------------------------
extern "C" void kernel_launch(void* const* d_in, const int* in_sizes, int n_in,
                              void* d_out, int out_size)
{
    const float* x    = (const float*)d_in[0];
    const float* ew   = (const float*)d_in[1];
    const float* W1   = (const float*)d_in[2];
    const float* b1   = (const float*)d_in[3];
    const float* W2   = (const float*)d_in[4];
    const float* b2   = (const float*)d_in[5];
    const float* W3   = (const float*)d_in[6];
    const float* b3   = (const float*)d_in[7];
    const int*   esrc = (const int*)d_in[8];
    const int*   edst = (const int*)d_in[9];

    const int n = in_sizes[0] / IN_DIM;   // 50000
    const int E = in_sizes[1];            // 1.6M

    __nv_bfloat16 *A1, *A2, *A3, *W1t, *W2t, *W3t;
    cudaGetSymbolAddress((void**)&A1,  g_A1v);
    cudaGetSymbolAddress((void**)&A2,  g_A2v);
    cudaGetSymbolAddress((void**)&A3,  g_A3v);
    cudaGetSymbolAddress((void**)&W1t, g_W1tv);
    cudaGetSymbolAddress((void**)&W2t, g_W2tv);
    cudaGetSymbolAddress((void**)&W3t, g_W3tv);

    cudaFuncSetAttribute(hmma_gemm<true, true>,
                         cudaFuncAttributeMaxDynamicSharedMemorySize, SMEM_BYTES);
    cudaFuncSetAttribute(hmma_gemm<false, false>,
                         cudaFuncAttributeMaxDynamicSharedMemorySize, SMEM_BYTES);

    // 1) zero agg
    {
        long long total = (long long)n * 128;
        zero_agg_kernel<<<(int)((total + 255) / 256), 256>>>(n);
    }
    // 2) all weight converts (fused)
    convert_w_all<<<dim3(64, 64, 3), dim3(32, 8)>>>(W1, W2, W3);
    // 3) scatter-add into agg
    spmm_kernel<<<(E + 7) / 8, 256>>>(x, ew, esrc, edst, E);
    // 4) split-convert [x|agg] -> A1
    {
        size_t t = (size_t)n * 512;
        convert_h_kernel<<<(int)((t + 255) / 256), 256>>>(x, n);
    }

    const int gy = (n + 127) / 128;   // 391
    // 5) layer 1: A2 = pack(relu(split(A1) @ split(W1t)^T + b1))   K=1024
    hmma_gemm<true, true><<<dim3(HDIM / 256, gy), 256, SMEM_BYTES>>>(
        A1, W1t, b1, (void*)A2, n, 1024, HDIM);
    // 6) layer 2: A3 = pack(relu(split(A2) @ split(W2t)^T + b2))   K=2048
    hmma_gemm<true, true><<<dim3(HDIM / 256, gy), 256, SMEM_BYTES>>>(
        A2, W2t, b2, (void*)A3, n, 2048, HDIM);
    // 7) layer 3: out = split(A3) @ split(W3t)^T + b3   (fp32)     K=2048
    hmma_gemm<false, false><<<dim3(OUT_DIM / 256, gy), 256, SMEM_BYTES>>>(
        A3, W3t, b3, d_out, n, 2048, OUT_DIM);
}

// round 9
// speedup vs baseline: 1.0088x; 1.0088x over previous
#include <cuda_runtime.h>
#include <cuda_bf16.h>
#include <cstdint>
#include <cstddef>

#define N_NODES 50000
#define IN_DIM  512
#define HDIM    2048
#define OUT_DIM 512

// ---------------------------------------------------------------------------
// Device-global scratch (allocation-free per harness rules).
// Split-bf16 operands stored compact as [hi | lo] (width 2K); GEMM tile
// loaders expand to the 3-term product via k-tile remapping.
// ---------------------------------------------------------------------------
__device__ float4 g_aggv[(size_t)N_NODES * 128];                    // agg fp32 (512/row)
__device__ float4 g_A1v [(size_t)N_NODES * 2048 / 8];               // [hi|lo] of h   (K=1024)
__device__ float4 g_A2v [(size_t)N_NODES * 4096 / 8];               // [hi|lo] layer1 (K=2048)
__device__ float4 g_A3v [(size_t)N_NODES * 4096 / 8];               // [hi|lo] layer2 (K=2048)
__device__ float4 g_W1tv[(size_t)HDIM    * 2048 / 8];               // [N, 2K] transposed
__device__ float4 g_W2tv[(size_t)HDIM    * 4096 / 8];
__device__ float4 g_W3tv[(size_t)OUT_DIM * 4096 / 8];

// ---------------------------------------------------------------------------
// PTX helpers (base compute_103 features only: cp.async / ldmatrix / mma.sync)
// ---------------------------------------------------------------------------
__device__ __forceinline__ uint32_t smem_u32(const void* p) {
    uint32_t a;
    asm("{ .reg .u64 t; cvta.to.shared.u64 t, %1; cvt.u32.u64 %0, t; }"
        : "=r"(a) : "l"(p));
    return a;
}
__device__ __forceinline__ void cp_async16(uint32_t dst, const void* src, bool pred) {
    int sz = pred ? 16 : 0;
    asm volatile("cp.async.cg.shared.global [%0], [%1], 16, %2;"
                 :: "r"(dst), "l"(src), "r"(sz));
}
__device__ __forceinline__ void cp_commit() { asm volatile("cp.async.commit_group;"); }
__device__ __forceinline__ void cp_wait1()  { asm volatile("cp.async.wait_group 1;" ::: "memory"); }
__device__ __forceinline__ void cp_wait0()  { asm volatile("cp.async.wait_group 0;" ::: "memory"); }

__device__ __forceinline__ void ldmx4(uint32_t& r0, uint32_t& r1, uint32_t& r2, uint32_t& r3,
                                      uint32_t addr) {
    asm volatile("ldmatrix.sync.aligned.m8n8.x4.shared.b16 {%0,%1,%2,%3}, [%4];"
                 : "=r"(r0), "=r"(r1), "=r"(r2), "=r"(r3) : "r"(addr));
}
__device__ __forceinline__ void mma16816(float* c, const uint32_t* a, const uint32_t* b) {
    asm volatile(
        "mma.sync.aligned.m16n8k16.row.col.f32.bf16.bf16.f32 "
        "{%0,%1,%2,%3}, {%4,%5,%6,%7}, {%8,%9}, {%0,%1,%2,%3};"
        : "+f"(c[0]), "+f"(c[1]), "+f"(c[2]), "+f"(c[3])
        : "r"(a[0]), "r"(a[1]), "r"(a[2]), "r"(a[3]), "r"(b[0]), "r"(b[1]));
}
__device__ __forceinline__ void red_add_v4(float* p, float4 v) {
    asm volatile("red.global.add.v4.f32 [%0], {%1,%2,%3,%4};"
                 :: "l"(p), "f"(v.x), "f"(v.y), "f"(v.z), "f"(v.w) : "memory");
}
__device__ __forceinline__ uint32_t swz(uint32_t off) {       // SW128 swizzle
    return off ^ ((off >> 3) & 0x70);
}
// k-tile remap for in-loader 3-term split expansion:
// logical regions over A: {hi, hi, lo};  over B: {hi, lo, hi}
__device__ __forceinline__ int skt_a(int kt, int T1) { return (kt < T1) ? kt : kt - T1; }
__device__ __forceinline__ int skt_b(int kt, int T1) { return (kt < 2 * T1) ? kt : kt - 2 * T1; }

// ---------------------------------------------------------------------------
// Kernel 1 (prep): z = 0..2 -> weight split-convert+transpose (32x32 tiles)
//                  z = 3    -> zero the aggregation buffer
// ---------------------------------------------------------------------------
__global__ void prep_kernel(const float* __restrict__ W1, const float* __restrict__ W2,
                            const float* __restrict__ W3, int n)
{
    if (blockIdx.z == 3) {
        const int tid = threadIdx.y * 32 + threadIdx.x;
        size_t total = (size_t)n * 128;
        size_t stride = (size_t)gridDim.x * gridDim.y * 256;
        size_t start = ((size_t)blockIdx.y * gridDim.x + blockIdx.x) * 256 + tid;
        for (size_t i = start; i < total; i += stride)
            g_aggv[i] = make_float4(0.f, 0.f, 0.f, 0.f);
        return;
    }
    __shared__ float tile[32][33];
    const float* W; __nv_bfloat16* Wt; int K, N;
    if (blockIdx.z == 0)      { W = W1; Wt = (__nv_bfloat16*)g_W1tv; K = 1024; N = 2048; }
    else if (blockIdx.z == 1) { W = W2; Wt = (__nv_bfloat16*)g_W2tv; K = 2048; N = 2048; }
    else                      { W = W3; Wt = (__nv_bfloat16*)g_W3tv; K = 2048; N = 512;  }
    const int k0 = blockIdx.y * 32;
    const int n0 = blockIdx.x * 32;
    if (k0 >= K || n0 >= N) return;
    const int tx = threadIdx.x;
#pragma unroll
    for (int r = threadIdx.y; r < 32; r += 8)
        tile[r][tx] = W[(size_t)(k0 + r) * N + n0 + tx];
    __syncthreads();
#pragma unroll
    for (int r = threadIdx.y; r < 32; r += 8) {
        int nn = n0 + r;
        int k  = k0 + tx;
        float v = tile[tx][r];
        __nv_bfloat16 hi = __float2bfloat16(v);
        __nv_bfloat16 lo = __float2bfloat16(v - __bfloat162float(hi));
        size_t base = (size_t)nn * (2 * (size_t)K);
        Wt[base + k]     = hi;
        Wt[base + K + k] = lo;
    }
}

// ---------------------------------------------------------------------------
// Kernel 2: SpMM scatter (warp per edge) — vectorized fp32 atomics (red.v4)
// ---------------------------------------------------------------------------
__global__ void spmm_kernel(const float* __restrict__ x, const float* __restrict__ ew,
                            const int* __restrict__ src, const int* __restrict__ dst, int E)
{
    int w    = (blockIdx.x * blockDim.x + threadIdx.x) >> 5;
    int lane = threadIdx.x & 31;
    if (w >= E) return;
    int   s  = __ldg(src + w);
    int   d  = __ldg(dst + w);
    float wt = __ldg(ew + w);
    const float4* xs = (const float4*)(x + (long long)s * IN_DIM);
    float4* out4 = g_aggv + (long long)d * 128;
#pragma unroll
    for (int i = 0; i < 4; i++) {
        int idx = lane + 32 * i;
        float4 v = __ldg(xs + idx);
        float4 m = make_float4(wt * v.x, wt * v.y, wt * v.z, wt * v.w);
        red_add_v4((float*)(out4 + idx), m);
    }
}

// ---------------------------------------------------------------------------
// Kernel 3: split-convert [x | agg] -> A1 [hi|lo] bf16 [M, 2048]
// ---------------------------------------------------------------------------
__global__ void convert_h_kernel(const float* __restrict__ x, int M)
{
    __nv_bfloat16* A1 = (__nv_bfloat16*)g_A1v;
    size_t i = (size_t)blockIdx.x * blockDim.x + threadIdx.x;   // float2 units
    size_t total = (size_t)M * 512;
    if (i >= total) return;
    int m  = (int)(i >> 9);
    int k2 = (int)(i & 511);
    float2 v = (k2 < 256)
        ? ((const float2*)x)[(size_t)m * 256 + k2]
        : ((const float2*)g_aggv)[(size_t)m * 256 + (k2 - 256)];
    __nv_bfloat16 h0 = __float2bfloat16(v.x), h1 = __float2bfloat16(v.y);
    __nv_bfloat16 l0 = __float2bfloat16(v.x - __bfloat162float(h0));
    __nv_bfloat16 l1 = __float2bfloat16(v.y - __bfloat162float(h1));
    __nv_bfloat162* row = (__nv_bfloat162*)(A1 + (size_t)m * 2048);
    row[k2]       = __halves2bfloat162(h0, h1);
    row[512 + k2] = __halves2bfloat162(l0, l1);
}

// ---------------------------------------------------------------------------
// Kernel 4: HMMA (mma.sync bf16) GEMM with in-loader 3-term split expansion.
//   C[M,Nc] = act(A[M,2K]{hi|lo} *split* Bt[Nc,2K]{hi|lo}^T + bias)
// Logical K' = 3K: region0 = Ahi*Bhi, region1 = Ahi*Blo, region2 = Alo*Bhi.
// BM=BN=128, BK=64, 8 warps (warp tile 32x64), 3-stage cp.async ring,
// single __syncthreads per k-tile, SW128 smem, 2 CTAs/SM.
// PACK: write [hi|lo] split output with row stride 2*Nc.
// ---------------------------------------------------------------------------
#define STAGE_BYTES 32768           // 16KB A + 16KB B
#define SMEM_BYTES  (3 * STAGE_BYTES)

__device__ __forceinline__ void load_tile_A(const __nv_bfloat16* A, int bm, int M, int strideA,
                                            int skt, uint32_t sdst, int tid)
{
#pragma unroll
    for (int i = 0; i < 4; i++) {
        int c = tid + i * 256;              // 0..1023 16B-chunks (128 rows x 8)
        int row = c >> 3, c16 = c & 7;
        int rm = bm + row;
        bool ok = rm < M;
        int rs = ok ? rm : (M - 1);
        const void* src = (const char*)(A + (size_t)rs * strideA + skt * 64) + c16 * 16;
        cp_async16(sdst + swz(row * 128 + c16 * 16), src, ok);
    }
}
__device__ __forceinline__ void load_tile_B(const __nv_bfloat16* Bt, int bn, int strideB,
                                            int skt, uint32_t sdst, int tid)
{
#pragma unroll
    for (int i = 0; i < 4; i++) {
        int c = tid + i * 256;              // 0..1023 (128 rows x 8)
        int row = c >> 3, c16 = c & 7;
        const void* src = (const char*)(Bt + (size_t)(bn + row) * strideB + skt * 64) + c16 * 16;
        cp_async16(sdst + swz(row * 128 + c16 * 16), src, true);
    }
}

template <bool RELU, bool PACK>
__global__ void __launch_bounds__(256, 2)
hmma_gemm(const __nv_bfloat16* __restrict__ A, const __nv_bfloat16* __restrict__ Bt,
          const float* __restrict__ bias, void* __restrict__ Cout,
          int M, int K, int Nc)
{
    extern __shared__ __align__(1024) char smem[];
    const uint32_t sb = smem_u32(smem);
    const int tid  = threadIdx.x;
    const int wid  = tid >> 5;
    const int lane = tid & 31;
    const int warp_m = wid & 3;        // 4 warps along M (32 rows each)
    const int warp_n = wid >> 2;       // 2 warps along N (64 cols each)
    const int bm = blockIdx.y * 128;
    const int bn = blockIdx.x * 128;
    const int strideA = 2 * K;         // stored width
    const int strideB = 2 * K;

    const int j = lane >> 3;
    const int r = lane & 7;

    float acc[2][8][4];
#pragma unroll
    for (int mt = 0; mt < 2; mt++)
#pragma unroll
        for (int nt = 0; nt < 8; nt++)
#pragma unroll
            for (int q = 0; q < 4; q++) acc[mt][nt][q] = 0.f;

    const int T1 = K / 64;             // tiles per K region
    const int T  = 3 * T1;             // logical k-tiles

    // prologue: stages 0,1
    load_tile_A(A, bm, M, strideA, skt_a(0, T1), sb + 0 * STAGE_BYTES, tid);
    load_tile_B(Bt, bn, strideB, skt_b(0, T1), sb + 0 * STAGE_BYTES + 16384, tid);
    cp_commit();
    load_tile_A(A, bm, M, strideA, skt_a(1, T1), sb + 1 * STAGE_BYTES, tid);
    load_tile_B(Bt, bn, strideB, skt_b(1, T1), sb + 1 * STAGE_BYTES + 16384, tid);
    cp_commit();

    const int amrow0 = warp_m * 32 + (j & 1) * 8 + r;    // + mt*16
    const int akoff  = (j >> 1) * 16;                    // + ks*32 bytes
    const int bnrow0 = warp_n * 64 + (j >> 1) * 8 + r;   // + nb*16
    const int bkoff  = (j & 1) * 16;

    int stage = 0;
    for (int kt = 0; kt < T; kt++) {
        if (kt == T - 1) cp_wait0(); else cp_wait1();
        __syncthreads();
        const uint32_t sA = sb + stage * STAGE_BYTES;
        const uint32_t sB = sA + 16384;

#pragma unroll
        for (int ks = 0; ks < 4; ks++) {
            uint32_t a[2][4], b[8][2];
#pragma unroll
            for (int mt = 0; mt < 2; mt++) {
                uint32_t addr = sA + swz((uint32_t)(amrow0 + mt * 16) * 128 +
                                         (uint32_t)(ks * 32 + akoff));
                ldmx4(a[mt][0], a[mt][1], a[mt][2], a[mt][3], addr);
            }
#pragma unroll
            for (int nb = 0; nb < 4; nb++) {
                uint32_t addr = sB + swz((uint32_t)(bnrow0 + nb * 16) * 128 +
                                         (uint32_t)(ks * 32 + bkoff));
                uint32_t t0, t1, t2, t3;
                ldmx4(t0, t1, t2, t3, addr);
                b[2 * nb][0] = t0; b[2 * nb][1] = t1;
                b[2 * nb + 1][0] = t2; b[2 * nb + 1][1] = t3;
            }
#pragma unroll
            for (int mt = 0; mt < 2; mt++)
#pragma unroll
                for (int nt = 0; nt < 8; nt++)
                    mma16816(acc[mt][nt], a[mt], b[nt]);
        }

        if (kt + 2 < T) {
            int ns = stage + 2; if (ns >= 3) ns -= 3;
            load_tile_A(A, bm, M, strideA, skt_a(kt + 2, T1), sb + ns * STAGE_BYTES, tid);
            load_tile_B(Bt, bn, strideB, skt_b(kt + 2, T1), sb + ns * STAGE_BYTES + 16384, tid);
            cp_commit();
        }
        if (++stage == 3) stage = 0;
    }

    // ------------------------- epilogue -------------------------
    const int row0 = bm + warp_m * 32;
    const int col0 = bn + warp_n * 64;
#pragma unroll
    for (int mt = 0; mt < 2; mt++) {
#pragma unroll
        for (int nt = 0; nt < 8; nt++) {
            const int gc = col0 + nt * 8 + 2 * (lane & 3);
            const float bi0 = __ldg(bias + gc);
            const float bi1 = __ldg(bias + gc + 1);
#pragma unroll
            for (int half = 0; half < 2; half++) {
                const int m = row0 + mt * 16 + (lane >> 2) + half * 8;
                if (m >= M) continue;
                float v0 = acc[mt][nt][half * 2 + 0] + bi0;
                float v1 = acc[mt][nt][half * 2 + 1] + bi1;
                if (RELU) { v0 = fmaxf(v0, 0.f); v1 = fmaxf(v1, 0.f); }
                if (PACK) {
                    __nv_bfloat16 h0 = __float2bfloat16(v0), h1 = __float2bfloat16(v1);
                    __nv_bfloat16 l0 = __float2bfloat16(v0 - __bfloat162float(h0));
                    __nv_bfloat16 l1 = __float2bfloat16(v1 - __bfloat162float(h1));
                    __nv_bfloat16* O = (__nv_bfloat16*)Cout;
                    const size_t base = (size_t)m * (2 * (size_t)Nc);
                    *(__nv_bfloat162*)(O + base + gc)      = __halves2bfloat162(h0, h1);
                    *(__nv_bfloat162*)(O + base + Nc + gc) = __halves2bfloat162(l0, l1);
                } else {
                    float* O = (float*)Cout;
                    *(float2*)(O + (size_t)m * Nc + gc) = make_float2(v0, v1);
                }
            }
        }
    }
}

// ---------------------------------------------------------------------------
// Launcher. 6 launches; GEMM1 is launch #4 (the slot ncu consistently samples).
// ---------------------------------------------------------------------------
extern "C" void kernel_launch(void* const* d_in, const int* in_sizes, int n_in,
                              void* d_out, int out_size)
{
    const float* x    = (const float*)d_in[0];
    const float* ew   = (const float*)d_in[1];
    const float* W1   = (const float*)d_in[2];
    const float* b1   = (const float*)d_in[3];
    const float* W2   = (const float*)d_in[4];
    const float* b2   = (const float*)d_in[5];
    const float* W3   = (const float*)d_in[6];
    const float* b3   = (const float*)d_in[7];
    const int*   esrc = (const int*)d_in[8];
    const int*   edst = (const int*)d_in[9];

    const int n = in_sizes[0] / IN_DIM;   // 50000
    const int E = in_sizes[1];            // 1.6M

    __nv_bfloat16 *A1, *A2, *A3, *W1t, *W2t, *W3t;
    cudaGetSymbolAddress((void**)&A1,  g_A1v);
    cudaGetSymbolAddress((void**)&A2,  g_A2v);
    cudaGetSymbolAddress((void**)&A3,  g_A3v);
    cudaGetSymbolAddress((void**)&W1t, g_W1tv);
    cudaGetSymbolAddress((void**)&W2t, g_W2tv);
    cudaGetSymbolAddress((void**)&W3t, g_W3tv);

    cudaFuncSetAttribute(hmma_gemm<true, true>,
                         cudaFuncAttributeMaxDynamicSharedMemorySize, SMEM_BYTES);
    cudaFuncSetAttribute(hmma_gemm<false, false>,
                         cudaFuncAttributeMaxDynamicSharedMemorySize, SMEM_BYTES);

    // 1) prep: weight converts (z=0..2) + zero agg (z=3)
    prep_kernel<<<dim3(64, 64, 4), dim3(32, 8)>>>(W1, W2, W3, n);
    // 2) scatter-add into agg
    spmm_kernel<<<(E + 7) / 8, 256>>>(x, ew, esrc, edst, E);
    // 3) split-convert [x|agg] -> A1
    {
        size_t t = (size_t)n * 512;
        convert_h_kernel<<<(int)((t + 255) / 256), 256>>>(x, n);
    }

    const int gy = (n + 127) / 128;   // 391
    // 4) layer 1: A2 = pack(relu(split(A1) @ split(W1t)^T + b1))   K=1024
    hmma_gemm<true, true><<<dim3(HDIM / 128, gy), 256, SMEM_BYTES>>>(
        A1, W1t, b1, (void*)A2, n, 1024, HDIM);
    // 5) layer 2: A3 = pack(relu(split(A2) @ split(W2t)^T + b2))   K=2048
    hmma_gemm<true, true><<<dim3(HDIM / 128, gy), 256, SMEM_BYTES>>>(
        A2, W2t, b2, (void*)A3, n, 2048, HDIM);
    // 6) layer 3: out = split(A3) @ split(W3t)^T + b3   (fp32)     K=2048
    hmma_gemm<false, false><<<dim3(OUT_DIM / 128, gy), 256, SMEM_BYTES>>>(
        A3, W3t, b3, d_out, n, 2048, OUT_DIM);
}

// round 10
// speedup vs baseline: 1.0401x; 1.0311x over previous
#include <cuda_runtime.h>
#include <cuda_bf16.h>
#include <cstdint>
#include <cstddef>

#define N_NODES 50000
#define IN_DIM  512
#define HDIM    2048
#define OUT_DIM 512

// ---------------------------------------------------------------------------
// Device-global scratch (allocation-free per harness rules).
// Split-bf16 operands stored compact as [hi | lo] (width 2K); GEMM tile
// loaders expand to the 3-term product via k-tile remapping.
// ---------------------------------------------------------------------------
__device__ float4 g_aggv[(size_t)N_NODES * 128];                    // agg fp32 (512/row)
__device__ float4 g_A1v [(size_t)N_NODES * 2048 / 8];               // [hi|lo] of h   (K=1024)
__device__ float4 g_A2v [(size_t)N_NODES * 4096 / 8];               // [hi|lo] layer1 (K=2048)
__device__ float4 g_A3v [(size_t)N_NODES * 4096 / 8];               // [hi|lo] layer2 (K=2048)
__device__ float4 g_W1tv[(size_t)HDIM    * 2048 / 8];               // [N, 2K] transposed
__device__ float4 g_W2tv[(size_t)HDIM    * 4096 / 8];
__device__ float4 g_W3tv[(size_t)OUT_DIM * 4096 / 8];

// ---------------------------------------------------------------------------
// PTX helpers (base compute_103 features only: cp.async / ldmatrix / mma.sync)
// ---------------------------------------------------------------------------
__device__ __forceinline__ uint32_t smem_u32(const void* p) {
    uint32_t a;
    asm("{ .reg .u64 t; cvta.to.shared.u64 t, %1; cvt.u32.u64 %0, t; }"
        : "=r"(a) : "l"(p));
    return a;
}
__device__ __forceinline__ void cp_async16(uint32_t dst, const void* src, bool pred) {
    int sz = pred ? 16 : 0;
    asm volatile("cp.async.cg.shared.global [%0], [%1], 16, %2;"
                 :: "r"(dst), "l"(src), "r"(sz));
}
__device__ __forceinline__ void cp_commit() { asm volatile("cp.async.commit_group;"); }
__device__ __forceinline__ void cp_wait1()  { asm volatile("cp.async.wait_group 1;" ::: "memory"); }
__device__ __forceinline__ void cp_wait0()  { asm volatile("cp.async.wait_group 0;" ::: "memory"); }

__device__ __forceinline__ void ldmx4(uint32_t& r0, uint32_t& r1, uint32_t& r2, uint32_t& r3,
                                      uint32_t addr) {
    asm volatile("ldmatrix.sync.aligned.m8n8.x4.shared.b16 {%0,%1,%2,%3}, [%4];"
                 : "=r"(r0), "=r"(r1), "=r"(r2), "=r"(r3) : "r"(addr));
}
__device__ __forceinline__ void mma16816(float* c, const uint32_t* a, const uint32_t* b) {
    asm volatile(
        "mma.sync.aligned.m16n8k16.row.col.f32.bf16.bf16.f32 "
        "{%0,%1,%2,%3}, {%4,%5,%6,%7}, {%8,%9}, {%0,%1,%2,%3};"
        : "+f"(c[0]), "+f"(c[1]), "+f"(c[2]), "+f"(c[3])
        : "r"(a[0]), "r"(a[1]), "r"(a[2]), "r"(a[3]), "r"(b[0]), "r"(b[1]));
}
__device__ __forceinline__ void red_add_v4(float* p, float4 v) {
    asm volatile("red.global.add.v4.f32 [%0], {%1,%2,%3,%4};"
                 :: "l"(p), "f"(v.x), "f"(v.y), "f"(v.z), "f"(v.w) : "memory");
}
__device__ __forceinline__ uint32_t swz(uint32_t off) {       // SW128 swizzle
    return off ^ ((off >> 3) & 0x70);
}
// k-tile remap for in-loader 3-term split expansion:
// logical regions over A: {hi, hi, lo};  over B: {hi, lo, hi}
__device__ __forceinline__ int skt_a(int kt, int T1) { return (kt < T1) ? kt : kt - T1; }
__device__ __forceinline__ int skt_b(int kt, int T1) { return (kt < 2 * T1) ? kt : kt - 2 * T1; }

// ---------------------------------------------------------------------------
// Kernel 1 (prep): z = 0..2 -> weight split-convert+transpose (32x32 tiles)
//                  z = 3    -> zero the aggregation buffer
// ---------------------------------------------------------------------------
__global__ void prep_kernel(const float* __restrict__ W1, const float* __restrict__ W2,
                            const float* __restrict__ W3, int n)
{
    if (blockIdx.z == 3) {
        const int tid = threadIdx.y * 32 + threadIdx.x;
        size_t total = (size_t)n * 128;
        size_t stride = (size_t)gridDim.x * gridDim.y * 256;
        size_t start = ((size_t)blockIdx.y * gridDim.x + blockIdx.x) * 256 + tid;
        for (size_t i = start; i < total; i += stride)
            g_aggv[i] = make_float4(0.f, 0.f, 0.f, 0.f);
        return;
    }
    __shared__ float tile[32][33];
    const float* W; __nv_bfloat16* Wt; int K, N;
    if (blockIdx.z == 0)      { W = W1; Wt = (__nv_bfloat16*)g_W1tv; K = 1024; N = 2048; }
    else if (blockIdx.z == 1) { W = W2; Wt = (__nv_bfloat16*)g_W2tv; K = 2048; N = 2048; }
    else                      { W = W3; Wt = (__nv_bfloat16*)g_W3tv; K = 2048; N = 512;  }
    const int k0 = blockIdx.y * 32;
    const int n0 = blockIdx.x * 32;
    if (k0 >= K || n0 >= N) return;
    const int tx = threadIdx.x;
#pragma unroll
    for (int r = threadIdx.y; r < 32; r += 8)
        tile[r][tx] = W[(size_t)(k0 + r) * N + n0 + tx];
    __syncthreads();
#pragma unroll
    for (int r = threadIdx.y; r < 32; r += 8) {
        int nn = n0 + r;
        int k  = k0 + tx;
        float v = tile[tx][r];
        __nv_bfloat16 hi = __float2bfloat16(v);
        __nv_bfloat16 lo = __float2bfloat16(v - __bfloat162float(hi));
        size_t base = (size_t)nn * (2 * (size_t)K);
        Wt[base + k]     = hi;
        Wt[base + K + k] = lo;
    }
}

// ---------------------------------------------------------------------------
// Kernel 2: SpMM scatter (warp per edge) — vectorized fp32 atomics (red.v4)
// ---------------------------------------------------------------------------
__global__ void spmm_kernel(const float* __restrict__ x, const float* __restrict__ ew,
                            const int* __restrict__ src, const int* __restrict__ dst, int E)
{
    int w    = (blockIdx.x * blockDim.x + threadIdx.x) >> 5;
    int lane = threadIdx.x & 31;
    if (w >= E) return;
    int   s  = __ldg(src + w);
    int   d  = __ldg(dst + w);
    float wt = __ldg(ew + w);
    const float4* xs = (const float4*)(x + (long long)s * IN_DIM);
    float4* out4 = g_aggv + (long long)d * 128;
#pragma unroll
    for (int i = 0; i < 4; i++) {
        int idx = lane + 32 * i;
        float4 v = __ldg(xs + idx);
        float4 m = make_float4(wt * v.x, wt * v.y, wt * v.z, wt * v.w);
        red_add_v4((float*)(out4 + idx), m);
    }
}

// ---------------------------------------------------------------------------
// Kernel 3: split-convert [x | agg] -> A1 [hi|lo] bf16 [M, 2048]
// ---------------------------------------------------------------------------
__global__ void convert_h_kernel(const float* __restrict__ x, int M)
{
    __nv_bfloat16* A1 = (__nv_bfloat16*)g_A1v;
    size_t i = (size_t)blockIdx.x * blockDim.x + threadIdx.x;   // float2 units
    size_t total = (size_t)M * 512;
    if (i >= total) return;
    int m  = (int)(i >> 9);
    int k2 = (int)(i & 511);
    float2 v = (k2 < 256)
        ? ((const float2*)x)[(size_t)m * 256 + k2]
        : ((const float2*)g_aggv)[(size_t)m * 256 + (k2 - 256)];
    __nv_bfloat16 h0 = __float2bfloat16(v.x), h1 = __float2bfloat16(v.y);
    __nv_bfloat16 l0 = __float2bfloat16(v.x - __bfloat162float(h0));
    __nv_bfloat16 l1 = __float2bfloat16(v.y - __bfloat162float(h1));
    __nv_bfloat162* row = (__nv_bfloat162*)(A1 + (size_t)m * 2048);
    row[k2]       = __halves2bfloat162(h0, h1);
    row[512 + k2] = __halves2bfloat162(l0, l1);
}

// ---------------------------------------------------------------------------
// Kernel 4: HMMA (mma.sync bf16) GEMM with in-loader 3-term split expansion.
//   C[M,Nc] = act(A[M,2K]{hi|lo} *split* Bt[Nc,2K]{hi|lo}^T + bias)
// Logical K' = 3K: region0 = Ahi*Bhi, region1 = Ahi*Blo, region2 = Alo*Bhi.
// BM=128, BN=256, BK=64; 8 warps in 2(M)x4(N) -> 64x64 warp tile
// (MMA:LDSM ratio 4.0 vs 2.67 of the 32x64 tile). 3-stage cp.async ring,
// single __syncthreads per k-tile, SW128 smem, 1 CTA/SM (144KB smem).
// PACK: write [hi|lo] split output with row stride 2*Nc.
// ---------------------------------------------------------------------------
#define STAGE_BYTES 49152           // 16KB A + 32KB B
#define SMEM_BYTES  (3 * STAGE_BYTES)

__device__ __forceinline__ void load_tile_A(const __nv_bfloat16* A, int bm, int M, int strideA,
                                            int skt, uint32_t sdst, int tid)
{
#pragma unroll
    for (int i = 0; i < 4; i++) {
        int c = tid + i * 256;              // 0..1023 16B-chunks (128 rows x 8)
        int row = c >> 3, c16 = c & 7;
        int rm = bm + row;
        bool ok = rm < M;
        int rs = ok ? rm : (M - 1);
        const void* src = (const char*)(A + (size_t)rs * strideA + skt * 64) + c16 * 16;
        cp_async16(sdst + swz(row * 128 + c16 * 16), src, ok);
    }
}
__device__ __forceinline__ void load_tile_B(const __nv_bfloat16* Bt, int bn, int strideB,
                                            int skt, uint32_t sdst, int tid)
{
#pragma unroll
    for (int i = 0; i < 8; i++) {
        int c = tid + i * 256;              // 0..2047 (256 rows x 8)
        int row = c >> 3, c16 = c & 7;
        const void* src = (const char*)(Bt + (size_t)(bn + row) * strideB + skt * 64) + c16 * 16;
        cp_async16(sdst + swz(row * 128 + c16 * 16), src, true);
    }
}

template <bool RELU, bool PACK>
__global__ void __launch_bounds__(256, 1)
hmma_gemm(const __nv_bfloat16* __restrict__ A, const __nv_bfloat16* __restrict__ Bt,
          const float* __restrict__ bias, void* __restrict__ Cout,
          int M, int K, int Nc)
{
    extern __shared__ __align__(1024) char smem[];
    const uint32_t sb = smem_u32(smem);
    const int tid  = threadIdx.x;
    const int wid  = tid >> 5;
    const int lane = tid & 31;
    const int warp_m = wid & 1;        // 2 warps along M (64 rows each)
    const int warp_n = wid >> 1;       // 4 warps along N (64 cols each)
    const int bm = blockIdx.y * 128;
    const int bn = blockIdx.x * 256;
    const int strideA = 2 * K;         // stored width
    const int strideB = 2 * K;

    const int j = lane >> 3;
    const int r = lane & 7;

    float acc[4][8][4];                // 64x64 per warp: 4 m16 x 8 n8
#pragma unroll
    for (int mt = 0; mt < 4; mt++)
#pragma unroll
        for (int nt = 0; nt < 8; nt++)
#pragma unroll
            for (int q = 0; q < 4; q++) acc[mt][nt][q] = 0.f;

    const int T1 = K / 64;             // tiles per K region
    const int T  = 3 * T1;             // logical k-tiles

    // prologue: stages 0,1
    load_tile_A(A, bm, M, strideA, skt_a(0, T1), sb + 0 * STAGE_BYTES, tid);
    load_tile_B(Bt, bn, strideB, skt_b(0, T1), sb + 0 * STAGE_BYTES + 16384, tid);
    cp_commit();
    load_tile_A(A, bm, M, strideA, skt_a(1, T1), sb + 1 * STAGE_BYTES, tid);
    load_tile_B(Bt, bn, strideB, skt_b(1, T1), sb + 1 * STAGE_BYTES + 16384, tid);
    cp_commit();

    const int amrow0 = warp_m * 64 + (j & 1) * 8 + r;    // + mt*16
    const int akoff  = (j >> 1) * 16;                    // + ks*32 bytes
    const int bnrow0 = warp_n * 64 + (j >> 1) * 8 + r;   // + nb*16
    const int bkoff  = (j & 1) * 16;

    int stage = 0;
    for (int kt = 0; kt < T; kt++) {
        if (kt == T - 1) cp_wait0(); else cp_wait1();
        __syncthreads();
        const uint32_t sA = sb + stage * STAGE_BYTES;
        const uint32_t sB = sA + 16384;

#pragma unroll
        for (int ks = 0; ks < 4; ks++) {
            uint32_t a[4][4], b[8][2];
#pragma unroll
            for (int mt = 0; mt < 4; mt++) {
                uint32_t addr = sA + swz((uint32_t)(amrow0 + mt * 16) * 128 +
                                         (uint32_t)(ks * 32 + akoff));
                ldmx4(a[mt][0], a[mt][1], a[mt][2], a[mt][3], addr);
            }
#pragma unroll
            for (int nb = 0; nb < 4; nb++) {
                uint32_t addr = sB + swz((uint32_t)(bnrow0 + nb * 16) * 128 +
                                         (uint32_t)(ks * 32 + bkoff));
                uint32_t t0, t1, t2, t3;
                ldmx4(t0, t1, t2, t3, addr);
                b[2 * nb][0] = t0; b[2 * nb][1] = t1;
                b[2 * nb + 1][0] = t2; b[2 * nb + 1][1] = t3;
            }
#pragma unroll
            for (int mt = 0; mt < 4; mt++)
#pragma unroll
                for (int nt = 0; nt < 8; nt++)
                    mma16816(acc[mt][nt], a[mt], b[nt]);
        }

        if (kt + 2 < T) {
            int ns = stage + 2; if (ns >= 3) ns -= 3;
            load_tile_A(A, bm, M, strideA, skt_a(kt + 2, T1), sb + ns * STAGE_BYTES, tid);
            load_tile_B(Bt, bn, strideB, skt_b(kt + 2, T1), sb + ns * STAGE_BYTES + 16384, tid);
            cp_commit();
        }
        if (++stage == 3) stage = 0;
    }

    // ------------------------- epilogue -------------------------
    const int row0 = bm + warp_m * 64;
    const int col0 = bn + warp_n * 64;
#pragma unroll
    for (int mt = 0; mt < 4; mt++) {
#pragma unroll
        for (int nt = 0; nt < 8; nt++) {
            const int gc = col0 + nt * 8 + 2 * (lane & 3);
            const float bi0 = __ldg(bias + gc);
            const float bi1 = __ldg(bias + gc + 1);
#pragma unroll
            for (int half = 0; half < 2; half++) {
                const int m = row0 + mt * 16 + (lane >> 2) + half * 8;
                if (m >= M) continue;
                float v0 = acc[mt][nt][half * 2 + 0] + bi0;
                float v1 = acc[mt][nt][half * 2 + 1] + bi1;
                if (RELU) { v0 = fmaxf(v0, 0.f); v1 = fmaxf(v1, 0.f); }
                if (PACK) {
                    __nv_bfloat16 h0 = __float2bfloat16(v0), h1 = __float2bfloat16(v1);
                    __nv_bfloat16 l0 = __float2bfloat16(v0 - __bfloat162float(h0));
                    __nv_bfloat16 l1 = __float2bfloat16(v1 - __bfloat162float(h1));
                    __nv_bfloat16* O = (__nv_bfloat16*)Cout;
                    const size_t base = (size_t)m * (2 * (size_t)Nc);
                    *(__nv_bfloat162*)(O + base + gc)      = __halves2bfloat162(h0, h1);
                    *(__nv_bfloat162*)(O + base + Nc + gc) = __halves2bfloat162(l0, l1);
                } else {
                    float* O = (float*)Cout;
                    *(float2*)(O + (size_t)m * Nc + gc) = make_float2(v0, v1);
                }
            }
        }
    }
}

// ---------------------------------------------------------------------------
// Launcher. 6 launches; GEMM1 is launch #4 (the slot ncu consistently samples).
// ---------------------------------------------------------------------------
extern "C" void kernel_launch(void* const* d_in, const int* in_sizes, int n_in,
                              void* d_out, int out_size)
{
    const float* x    = (const float*)d_in[0];
    const float* ew   = (const float*)d_in[1];
    const float* W1   = (const float*)d_in[2];
    const float* b1   = (const float*)d_in[3];
    const float* W2   = (const float*)d_in[4];
    const float* b2   = (const float*)d_in[5];
    const float* W3   = (const float*)d_in[6];
    const float* b3   = (const float*)d_in[7];
    const int*   esrc = (const int*)d_in[8];
    const int*   edst = (const int*)d_in[9];

    const int n = in_sizes[0] / IN_DIM;   // 50000
    const int E = in_sizes[1];            // 1.6M

    __nv_bfloat16 *A1, *A2, *A3, *W1t, *W2t, *W3t;
    cudaGetSymbolAddress((void**)&A1,  g_A1v);
    cudaGetSymbolAddress((void**)&A2,  g_A2v);
    cudaGetSymbolAddress((void**)&A3,  g_A3v);
    cudaGetSymbolAddress((void**)&W1t, g_W1tv);
    cudaGetSymbolAddress((void**)&W2t, g_W2tv);
    cudaGetSymbolAddress((void**)&W3t, g_W3tv);

    cudaFuncSetAttribute(hmma_gemm<true, true>,
                         cudaFuncAttributeMaxDynamicSharedMemorySize, SMEM_BYTES);
    cudaFuncSetAttribute(hmma_gemm<false, false>,
                         cudaFuncAttributeMaxDynamicSharedMemorySize, SMEM_BYTES);

    // 1) prep: weight converts (z=0..2) + zero agg (z=3)
    prep_kernel<<<dim3(64, 64, 4), dim3(32, 8)>>>(W1, W2, W3, n);
    // 2) scatter-add into agg
    spmm_kernel<<<(E + 7) / 8, 256>>>(x, ew, esrc, edst, E);
    // 3) split-convert [x|agg] -> A1
    {
        size_t t = (size_t)n * 512;
        convert_h_kernel<<<(int)((t + 255) / 256), 256>>>(x, n);
    }

    const int gy = (n + 127) / 128;   // 391
    // 4) layer 1: A2 = pack(relu(split(A1) @ split(W1t)^T + b1))   K=1024
    hmma_gemm<true, true><<<dim3(HDIM / 256, gy), 256, SMEM_BYTES>>>(
        A1, W1t, b1, (void*)A2, n, 1024, HDIM);
    // 5) layer 2: A3 = pack(relu(split(A2) @ split(W2t)^T + b2))   K=2048
    hmma_gemm<true, true><<<dim3(HDIM / 256, gy), 256, SMEM_BYTES>>>(
        A2, W2t, b2, (void*)A3, n, 2048, HDIM);
    // 6) layer 3: out = split(A3) @ split(W3t)^T + b3   (fp32)     K=2048
    hmma_gemm<false, false><<<dim3(OUT_DIM / 256, gy), 256, SMEM_BYTES>>>(
        A3, W3t, b3, d_out, n, 2048, OUT_DIM);
}